// round 1
// baseline (speedup 1.0000x reference)
#include <cuda_runtime.h>
#include <cstdint>

// Problem constants (fixed by the dataset)
// B=2, S=2048, H=1024, NH=16, D=64; M = B*S = 4096; 3H = 3072

static __device__ float g_qkv[4096 * 3072];   // qkv projection scratch (50.3 MB)
static __device__ float g_attn[4096 * 1024];  // attention output scratch (16.8 MB)

__device__ __forceinline__ uint32_t f2tf(float x) {
    uint32_t u;
    asm("cvt.rna.tf32.f32 %0, %1;" : "=r"(u) : "f"(x));
    return u;
}
__device__ __forceinline__ float tf2f(float x) { return __uint_as_float(f2tf(x)); }
__device__ __forceinline__ float ex2f(float x) {
    float y;
    asm("ex2.approx.f32 %0, %1;" : "=f"(y) : "f"(x));
    return y;
}

// D(16x8) += A(16x8, tf32, row-major) * B(8x8, tf32, col-major)
__device__ __forceinline__ void mma_tf32(float* c, const uint32_t* a, uint32_t b0, uint32_t b1) {
    asm volatile(
        "mma.sync.aligned.m16n8k8.row.col.f32.tf32.tf32.f32 "
        "{%0,%1,%2,%3},{%4,%5,%6,%7},{%8,%9},{%0,%1,%2,%3};\n"
        : "+f"(c[0]), "+f"(c[1]), "+f"(c[2]), "+f"(c[3])
        : "r"(a[0]), "r"(a[1]), "r"(a[2]), "r"(a[3]), "r"(b0), "r"(b1));
}

// ============================================================================
// Generic tf32 GEMM: C[M,N] = scale * A[M,K] @ B[K,N]   (all row-major fp32)
// CTA tile 128x128, BK=32, 256 threads (8 warps, 2x4), warp tile 64x32.
// Smem double-buffered; operands RNA-rounded to tf32 at the STS.
// ============================================================================
#define GM_SA (128 * 36)   // A tile 128x32, row stride 36 (bank-conflict-free frags)
#define GM_SB (32 * 136)   // B tile 32x128, row stride 136

__global__ __launch_bounds__(256) void gemm_tf32(
    const float* __restrict__ A, const float* __restrict__ Bm, float* __restrict__ C,
    int M, int N, int K, const float* __restrict__ scale_p)
{
    extern __shared__ float sm[];
    float* sA = sm;               // [2][128][36]
    float* sB = sm + 2 * GM_SA;   // [2][32][136]

    const int tid  = threadIdx.x;
    const int warp = tid >> 5, lane = tid & 31;
    const int wm = warp >> 2, wn = warp & 3;   // 2 warp-rows x 4 warp-cols
    const int g = lane >> 2, q = lane & 3;
    const int bx = blockIdx.x, by = blockIdx.y;

    // global load mapping
    const int arow = by * 128 + (tid >> 3);   // +p*32, p=0..3
    const int ac4  = (tid & 7) * 4;           // k-col within tile
    const int brow = (tid >> 5);              // +p*8, p=0..3
    const int bcol = bx * 128 + (tid & 31) * 4;

    float4 aR[4], bR[4];
#pragma unroll
    for (int p = 0; p < 4; p++)
        aR[p] = *reinterpret_cast<const float4*>(&A[(size_t)(arow + p * 32) * K + ac4]);
#pragma unroll
    for (int p = 0; p < 4; p++)
        bR[p] = *reinterpret_cast<const float4*>(&Bm[(size_t)(brow + p * 8) * N + bcol]);

    // store tile 0 into buffer 0 (converted to tf32)
#pragma unroll
    for (int p = 0; p < 4; p++) {
        float* d = &sA[((tid >> 3) + p * 32) * 36 + ac4];
        d[0] = tf2f(aR[p].x); d[1] = tf2f(aR[p].y); d[2] = tf2f(aR[p].z); d[3] = tf2f(aR[p].w);
    }
#pragma unroll
    for (int p = 0; p < 4; p++) {
        float* d = &sB[(brow + p * 8) * 136 + (tid & 31) * 4];
        d[0] = tf2f(bR[p].x); d[1] = tf2f(bR[p].y); d[2] = tf2f(bR[p].z); d[3] = tf2f(bR[p].w);
    }
    __syncthreads();

    float acc[4][4][4];
#pragma unroll
    for (int mf = 0; mf < 4; mf++)
#pragma unroll
        for (int nf = 0; nf < 4; nf++)
#pragma unroll
            for (int e = 0; e < 4; e++) acc[mf][nf][e] = 0.f;

    const int NK = K / 32;
    int cur = 0;
    for (int kt = 0; kt < NK; kt++) {
        if (kt + 1 < NK) {
            const int kc = (kt + 1) * 32;
#pragma unroll
            for (int p = 0; p < 4; p++)
                aR[p] = *reinterpret_cast<const float4*>(&A[(size_t)(arow + p * 32) * K + kc + ac4]);
#pragma unroll
            for (int p = 0; p < 4; p++)
                bR[p] = *reinterpret_cast<const float4*>(&Bm[(size_t)(kc + brow + p * 8) * N + bcol]);
        }
        const float* cA = sA + cur * GM_SA;
        const float* cB = sB + cur * GM_SB;
#pragma unroll
        for (int ks = 0; ks < 4; ks++) {
            uint32_t af[4][4];
#pragma unroll
            for (int mf = 0; mf < 4; mf++) {
                const int r = wm * 64 + mf * 16 + g;
                const int c = ks * 8 + q;
                af[mf][0] = __float_as_uint(cA[r * 36 + c]);
                af[mf][1] = __float_as_uint(cA[(r + 8) * 36 + c]);
                af[mf][2] = __float_as_uint(cA[r * 36 + c + 4]);
                af[mf][3] = __float_as_uint(cA[(r + 8) * 36 + c + 4]);
            }
#pragma unroll
            for (int nf = 0; nf < 4; nf++) {
                const int n = wn * 32 + nf * 8 + g;
                const int k = ks * 8 + q;
                const uint32_t b0 = __float_as_uint(cB[k * 136 + n]);
                const uint32_t b1 = __float_as_uint(cB[(k + 4) * 136 + n]);
#pragma unroll
                for (int mf = 0; mf < 4; mf++) mma_tf32(acc[mf][nf], af[mf], b0, b1);
            }
        }
        if (kt + 1 < NK) {
            float* dA = sA + (cur ^ 1) * GM_SA;
            float* dB = sB + (cur ^ 1) * GM_SB;
#pragma unroll
            for (int p = 0; p < 4; p++) {
                float* d = &dA[((tid >> 3) + p * 32) * 36 + ac4];
                d[0] = tf2f(aR[p].x); d[1] = tf2f(aR[p].y); d[2] = tf2f(aR[p].z); d[3] = tf2f(aR[p].w);
            }
#pragma unroll
            for (int p = 0; p < 4; p++) {
                float* d = &dB[(brow + p * 8) * 136 + (tid & 31) * 4];
                d[0] = tf2f(bR[p].x); d[1] = tf2f(bR[p].y); d[2] = tf2f(bR[p].z); d[3] = tf2f(bR[p].w);
            }
        }
        __syncthreads();
        cur ^= 1;
    }

    const float sc = scale_p ? *scale_p : 1.0f;
#pragma unroll
    for (int mf = 0; mf < 4; mf++) {
        const int r0 = by * 128 + wm * 64 + mf * 16 + g;
#pragma unroll
        for (int nf = 0; nf < 4; nf++) {
            const int c0 = bx * 128 + wn * 32 + nf * 8 + q * 2;
            *reinterpret_cast<float2*>(&C[(size_t)r0 * N + c0]) =
                make_float2(acc[mf][nf][0] * sc, acc[mf][nf][1] * sc);
            *reinterpret_cast<float2*>(&C[(size_t)(r0 + 8) * N + c0]) =
                make_float2(acc[mf][nf][2] * sc, acc[mf][nf][3] * sc);
        }
    }
}

// ============================================================================
// Fused flash attention (tf32 mma), no masking. One CTA = 128 q-rows of one
// (b, h). 8 warps x 16 q-rows. KV tiles of 128, 16 iterations. Q fragments
// register-resident (pre-scaled by 1/sqrt(d)); P round-trips through
// warp-private smem to convert C-fragment layout -> A-fragment layout.
// ============================================================================
#define FA_SK (128 * 68)
#define FA_SV (128 * 72)
#define FA_SP (128 * 132)

__global__ __launch_bounds__(256) void flash_tf32(
    const float* __restrict__ qkv, float* __restrict__ attn)
{
    extern __shared__ float sm[];
    float* sK = sm;                  // [128][68]  (B-operand of QK^T: n=kv, k=d)
    float* sV = sm + FA_SK;          // [128][72]  (B-operand of PV:   k=kv, n=d)
    float* sP = sm + FA_SK + FA_SV;  // [128][132] (A-operand of PV, warp-private rows)

    const int tid = threadIdx.x, warp = tid >> 5, lane = tid & 31;
    const int g = lane >> 2, q = lane & 3;
    const int qt = blockIdx.x, h = blockIdx.y, b = blockIdx.z;
    const float L2E = 1.4426950408889634f;

    const int qrow = b * 2048 + qt * 128 + warp * 16 + g;  // first of this thread's 2 rows
    const int qcol = h * 64;

    // Q fragments, register resident, pre-scaled by 1/sqrt(64)=0.125 (exact in tf32)
    uint32_t qa[8][4];
#pragma unroll
    for (int ks = 0; ks < 8; ks++) {
        const int c = qcol + ks * 8 + q;
        qa[ks][0] = f2tf(qkv[(size_t)qrow * 3072 + c] * 0.125f);
        qa[ks][1] = f2tf(qkv[(size_t)(qrow + 8) * 3072 + c] * 0.125f);
        qa[ks][2] = f2tf(qkv[(size_t)qrow * 3072 + c + 4] * 0.125f);
        qa[ks][3] = f2tf(qkv[(size_t)(qrow + 8) * 3072 + c + 4] * 0.125f);
    }

    float m0 = -1e30f, m1 = -1e30f, l0 = 0.f, l1 = 0.f;
    float o[8][4];
#pragma unroll
    for (int nf = 0; nf < 8; nf++)
#pragma unroll
        for (int e = 0; e < 4; e++) o[nf][e] = 0.f;

    const int rr0 = tid >> 4;        // 0..15
    const int dd  = (tid & 15) * 4;  // 0..60
    const int pr  = warp * 16 + g;   // warp-private P row

    for (int j = 0; j < 16; j++) {
        __syncthreads();  // previous tile's K/V reads done before overwrite
        const size_t kvbase = (size_t)(b * 2048 + j * 128) * 3072 + 1024 + (size_t)h * 64;
#pragma unroll
        for (int p = 0; p < 8; p++) {
            const int rr = rr0 + p * 16;
            const float4 kx = *reinterpret_cast<const float4*>(&qkv[kvbase + (size_t)rr * 3072 + dd]);
            float* dk = &sK[rr * 68 + dd];
            dk[0] = tf2f(kx.x); dk[1] = tf2f(kx.y); dk[2] = tf2f(kx.z); dk[3] = tf2f(kx.w);
            const float4 vx = *reinterpret_cast<const float4*>(&qkv[kvbase + 1024 + (size_t)rr * 3072 + dd]);
            float* dv = &sV[rr * 72 + dd];
            dv[0] = tf2f(vx.x); dv[1] = tf2f(vx.y); dv[2] = tf2f(vx.z); dv[3] = tf2f(vx.w);
        }
        __syncthreads();

        // S = Q @ K^T  (per warp: 16 q-rows x 128 kv-cols)
        float s[16][4];
#pragma unroll
        for (int nf = 0; nf < 16; nf++)
#pragma unroll
            for (int e = 0; e < 4; e++) s[nf][e] = 0.f;
#pragma unroll
        for (int ks = 0; ks < 8; ks++) {
#pragma unroll
            for (int nf = 0; nf < 16; nf++) {
                const uint32_t b0 = __float_as_uint(sK[(nf * 8 + g) * 68 + ks * 8 + q]);
                const uint32_t b1 = __float_as_uint(sK[(nf * 8 + g) * 68 + ks * 8 + q + 4]);
                mma_tf32(s[nf], qa[ks], b0, b1);
            }
        }

        // online softmax (rows r and r+8 per thread)
        float rm0 = -1e30f, rm1 = -1e30f;
#pragma unroll
        for (int nf = 0; nf < 16; nf++) {
            rm0 = fmaxf(rm0, fmaxf(s[nf][0], s[nf][1]));
            rm1 = fmaxf(rm1, fmaxf(s[nf][2], s[nf][3]));
        }
        rm0 = fmaxf(rm0, __shfl_xor_sync(0xffffffffu, rm0, 1));
        rm0 = fmaxf(rm0, __shfl_xor_sync(0xffffffffu, rm0, 2));
        rm1 = fmaxf(rm1, __shfl_xor_sync(0xffffffffu, rm1, 1));
        rm1 = fmaxf(rm1, __shfl_xor_sync(0xffffffffu, rm1, 2));
        const float mn0 = fmaxf(m0, rm0), mn1 = fmaxf(m1, rm1);
        const float al0 = ex2f((m0 - mn0) * L2E), al1 = ex2f((m1 - mn1) * L2E);
        const float mb0 = mn0 * L2E, mb1 = mn1 * L2E;

        float rs0 = 0.f, rs1 = 0.f;
#pragma unroll
        for (int nf = 0; nf < 16; nf++) {
            const float p0 = tf2f(ex2f(fmaf(s[nf][0], L2E, -mb0)));
            const float p1 = tf2f(ex2f(fmaf(s[nf][1], L2E, -mb0)));
            const float p2 = tf2f(ex2f(fmaf(s[nf][2], L2E, -mb1)));
            const float p3 = tf2f(ex2f(fmaf(s[nf][3], L2E, -mb1)));
            rs0 += p0 + p1;
            rs1 += p2 + p3;
            *reinterpret_cast<float2*>(&sP[pr * 132 + nf * 8 + q * 2]) = make_float2(p0, p1);
            *reinterpret_cast<float2*>(&sP[(pr + 8) * 132 + nf * 8 + q * 2]) = make_float2(p2, p3);
        }
        rs0 += __shfl_xor_sync(0xffffffffu, rs0, 1);
        rs0 += __shfl_xor_sync(0xffffffffu, rs0, 2);
        rs1 += __shfl_xor_sync(0xffffffffu, rs1, 1);
        rs1 += __shfl_xor_sync(0xffffffffu, rs1, 2);
        l0 = l0 * al0 + rs0;
        l1 = l1 * al1 + rs1;
        m0 = mn0; m1 = mn1;
#pragma unroll
        for (int nf = 0; nf < 8; nf++) {
            o[nf][0] *= al0; o[nf][1] *= al0; o[nf][2] *= al1; o[nf][3] *= al1;
        }
        __syncwarp();  // sP visible across the warp (warp-private rows; no CTA barrier needed)

        // O += P @ V
#pragma unroll
        for (int kb = 0; kb < 16; kb++) {
            uint32_t pa[4];
            pa[0] = __float_as_uint(sP[pr * 132 + kb * 8 + q]);
            pa[1] = __float_as_uint(sP[(pr + 8) * 132 + kb * 8 + q]);
            pa[2] = __float_as_uint(sP[pr * 132 + kb * 8 + q + 4]);
            pa[3] = __float_as_uint(sP[(pr + 8) * 132 + kb * 8 + q + 4]);
#pragma unroll
            for (int nf = 0; nf < 8; nf++) {
                const uint32_t b0 = __float_as_uint(sV[(kb * 8 + q) * 72 + nf * 8 + g]);
                const uint32_t b1 = __float_as_uint(sV[(kb * 8 + q + 4) * 72 + nf * 8 + g]);
                mma_tf32(o[nf], pa, b0, b1);
            }
        }
    }

    const float il0 = 1.f / l0, il1 = 1.f / l1;
#pragma unroll
    for (int nf = 0; nf < 8; nf++) {
        const int c = h * 64 + nf * 8 + q * 2;
        *reinterpret_cast<float2*>(&attn[(size_t)qrow * 1024 + c]) =
            make_float2(o[nf][0] * il0, o[nf][1] * il0);
        *reinterpret_cast<float2*>(&attn[(size_t)(qrow + 8) * 1024 + c]) =
            make_float2(o[nf][2] * il1, o[nf][3] * il1);
    }
}

// ============================================================================
// Launch: qkv = hidden @ Wqkv ; flash attention ; out = ss * (attn @ Wo)
// ============================================================================
extern "C" void kernel_launch(void* const* d_in, const int* in_sizes, int n_in,
                              void* d_out, int out_size)
{
    const float* hidden = (const float*)d_in[0];  // [2,2048,1024]
    const float* qkvw   = (const float*)d_in[1];  // [1024,3072]
    const float* ow     = (const float*)d_in[2];  // [1024,1024]
    const float* ssm    = (const float*)d_in[4];  // scalar scaled_softmax
    float* out = (float*)d_out;                   // [2,2048,1024]
    (void)in_sizes; (void)n_in; (void)out_size;

    const int smem_g = (2 * GM_SA + 2 * GM_SB) * 4;          // 71680 B
    const int smem_f = (FA_SK + FA_SV + FA_SP) * 4;          // 139264 B
    cudaFuncSetAttribute(gemm_tf32, cudaFuncAttributeMaxDynamicSharedMemorySize, smem_g);
    cudaFuncSetAttribute(flash_tf32, cudaFuncAttributeMaxDynamicSharedMemorySize, smem_f);

    float *qkvp, *attnp;
    cudaGetSymbolAddress((void**)&qkvp, g_qkv);
    cudaGetSymbolAddress((void**)&attnp, g_attn);

    // QKV projection: [4096,1024] @ [1024,3072] -> [4096,3072]
    gemm_tf32<<<dim3(3072 / 128, 4096 / 128), 256, smem_g>>>(
        hidden, qkvw, qkvp, 4096, 3072, 1024, nullptr);

    // attention: per (b,h,qtile=128)
    flash_tf32<<<dim3(16, 16, 2), 256, smem_f>>>(qkvp, attnp);

    // O projection (with scaled_softmax folded in): [4096,1024] @ [1024,1024]
    gemm_tf32<<<dim3(1024 / 128, 4096 / 128), 256, smem_g>>>(
        attnp, ow, out, 4096, 1024, 1024, ssm);
}